// round 2
// baseline (speedup 1.0000x reference)
#include <cuda_runtime.h>
#include <cuda_bf16.h>
#include <math.h>

#define D_MODEL 1024
#define SEQ     2048
#define NB      2
#define NTOK    (NB * SEQ)      // 4096 tokens
#define NHEAD   16
#define DHEAD   64
#define NEGV    (-1000000000.0f)

// ---------------------------------------------------------------------------
// Scratch buffers (static __device__ — no allocation allowed)
// ---------------------------------------------------------------------------
__device__ float g_x   [NTOK * D_MODEL];   // LN1(embed)
__device__ float g_q   [NTOK * D_MODEL];
__device__ float g_k   [NTOK * D_MODEL];
__device__ float g_v   [NTOK * D_MODEL];
__device__ float g_attn[NTOK * D_MODEL];
__device__ float g_h   [NTOK * D_MODEL];   // x + attn_proj
__device__ float g_hln [NTOK * D_MODEL];   // LN2(h)  (also the cross residual!)
__device__ float g_r   [NTOK * D_MODEL];   // cross_proj + hln
__device__ float g_z   [NTOK * D_MODEL];   // LN3(r)
__device__ float g_mh  [(size_t)NTOK * 4096]; // MLP hidden

// ---------------------------------------------------------------------------
// Block reduce (sum of two values) — 256 threads
// ---------------------------------------------------------------------------
__device__ __forceinline__ float2 block_reduce_sum2(float a, float b) {
    #pragma unroll
    for (int o = 16; o > 0; o >>= 1) {
        a += __shfl_xor_sync(0xffffffffu, a, o);
        b += __shfl_xor_sync(0xffffffffu, b, o);
    }
    __shared__ float sa[8], sb[8];
    int w = threadIdx.x >> 5;
    if ((threadIdx.x & 31) == 0) { sa[w] = a; sb[w] = b; }
    __syncthreads();
    float ta = 0.f, tb = 0.f;
    #pragma unroll
    for (int k = 0; k < 8; k++) { ta += sa[k]; tb += sb[k]; }
    return make_float2(ta, tb);
}

// ---------------------------------------------------------------------------
// Fused embedding + LayerNorm1. One block (256 thr) per token row of 1024.
// ---------------------------------------------------------------------------
__global__ void __launch_bounds__(256) embed_ln_kernel(
    const int* __restrict__ ids, const float* __restrict__ tok,
    const float* __restrict__ pos, const float* __restrict__ g,
    const float* __restrict__ be, float* __restrict__ out)
{
    int row = blockIdx.x;
    int s   = row & (SEQ - 1);
    int id  = ids[row];
    int i   = threadIdx.x;   // one float4 per thread (256*4 = 1024)

    float4 tv = ((const float4*)(tok + (size_t)id * D_MODEL))[i];
    float4 pv = ((const float4*)(pos + (size_t)s  * D_MODEL))[i];
    float4 v  = make_float4(tv.x + pv.x, tv.y + pv.y, tv.z + pv.z, tv.w + pv.w);

    float2 ss = block_reduce_sum2(v.x + v.y + v.z + v.w,
                                  v.x*v.x + v.y*v.y + v.z*v.z + v.w*v.w);
    float mean = ss.x * (1.f / D_MODEL);
    float var  = ss.y * (1.f / D_MODEL) - mean * mean;
    float rstd = rsqrtf(var + 1e-5f);

    float4 gv = ((const float4*)g)[i];
    float4 bv = ((const float4*)be)[i];
    float4 o  = make_float4((v.x - mean) * rstd * gv.x + bv.x,
                            (v.y - mean) * rstd * gv.y + bv.y,
                            (v.z - mean) * rstd * gv.z + bv.z,
                            (v.w - mean) * rstd * gv.w + bv.w);
    ((float4*)(out + (size_t)row * D_MODEL))[i] = o;
}

// ---------------------------------------------------------------------------
// Plain LayerNorm. One block per row of 1024.
// ---------------------------------------------------------------------------
__global__ void __launch_bounds__(256) ln_kernel(
    const float* __restrict__ in, const float* __restrict__ g,
    const float* __restrict__ be, float* __restrict__ out)
{
    int row = blockIdx.x;
    int i   = threadIdx.x;
    float4 v = ((const float4*)(in + (size_t)row * D_MODEL))[i];

    float2 ss = block_reduce_sum2(v.x + v.y + v.z + v.w,
                                  v.x*v.x + v.y*v.y + v.z*v.z + v.w*v.w);
    float mean = ss.x * (1.f / D_MODEL);
    float var  = ss.y * (1.f / D_MODEL) - mean * mean;
    float rstd = rsqrtf(var + 1e-5f);

    float4 gv = ((const float4*)g)[i];
    float4 bv = ((const float4*)be)[i];
    float4 o  = make_float4((v.x - mean) * rstd * gv.x + bv.x,
                            (v.y - mean) * rstd * gv.y + bv.y,
                            (v.z - mean) * rstd * gv.z + bv.z,
                            (v.w - mean) * rstd * gv.w + bv.w);
    ((float4*)(out + (size_t)row * D_MODEL))[i] = o;
}

// ---------------------------------------------------------------------------
// SGEMM: C[M,N] = A[M,K] @ B[K,N] + bias  (+ epilogue)
// 128x128 tile, BK=16, 256 threads, 8x8 microtile per thread.
// EPI: 0 = bias only, 1 = bias + residual, 2 = bias + exact GELU
// ---------------------------------------------------------------------------
template <int EPI>
__global__ void __launch_bounds__(256) gemm_kernel(
    const float* __restrict__ A, const float* __restrict__ B,
    const float* __restrict__ bias, const float* __restrict__ res,
    float* __restrict__ C, int M, int N, int K)
{
    __shared__ float As[16 * 128];   // transposed: As[k][m]
    __shared__ float Bs[16 * 128];   // natural:    Bs[k][n]

    const int tid = threadIdx.x;
    const int tx = tid & 15, ty = tid >> 4;
    const int row0 = blockIdx.y * 128;
    const int col0 = blockIdx.x * 128;

    float acc[64];
    #pragma unroll
    for (int i = 0; i < 64; i++) acc[i] = 0.f;

    for (int k0 = 0; k0 < K; k0 += 16) {
        __syncthreads();
        #pragma unroll
        for (int t = 0; t < 2; t++) {
            int qidx = tid * 2 + t;              // 0..511
            int ar  = qidx >> 2, ac4 = qidx & 3; // A: 128 rows x 4 float4
            float4 av = *(const float4*)(A + (size_t)(row0 + ar) * K + k0 + ac4 * 4);
            As[(ac4 * 4 + 0) * 128 + ar] = av.x;
            As[(ac4 * 4 + 1) * 128 + ar] = av.y;
            As[(ac4 * 4 + 2) * 128 + ar] = av.z;
            As[(ac4 * 4 + 3) * 128 + ar] = av.w;
            int br = qidx >> 5, bc4 = qidx & 31; // B: 16 rows x 32 float4
            float4 bv = *(const float4*)(B + (size_t)(k0 + br) * N + col0 + bc4 * 4);
            *(float4*)(Bs + br * 128 + bc4 * 4) = bv;
        }
        __syncthreads();
        #pragma unroll
        for (int kk = 0; kk < 16; kk++) {
            float4 a0 = *(const float4*)(As + kk * 128 + ty * 8);
            float4 a1 = *(const float4*)(As + kk * 128 + ty * 8 + 4);
            float4 b0 = *(const float4*)(Bs + kk * 128 + tx * 8);
            float4 b1 = *(const float4*)(Bs + kk * 128 + tx * 8 + 4);
            float areg[8] = {a0.x, a0.y, a0.z, a0.w, a1.x, a1.y, a1.z, a1.w};
            float breg[8] = {b0.x, b0.y, b0.z, b0.w, b1.x, b1.y, b1.z, b1.w};
            #pragma unroll
            for (int i = 0; i < 8; i++)
                #pragma unroll
                for (int j = 0; j < 8; j++)
                    acc[i * 8 + j] += areg[i] * breg[j];
        }
    }

    // epilogue (vectorized)
    #pragma unroll
    for (int i = 0; i < 8; i++) {
        int rr = row0 + ty * 8 + i;
        float*       crow = C + (size_t)rr * N + col0 + tx * 8;
        const float* rrow = (EPI == 1) ? (res + (size_t)rr * N + col0 + tx * 8) : (const float*)0;
        #pragma unroll
        for (int jj = 0; jj < 2; jj++) {
            const float* bptr = bias + col0 + tx * 8 + jj * 4;
            float4 v;
            v.x = acc[i * 8 + jj * 4 + 0] + bptr[0];
            v.y = acc[i * 8 + jj * 4 + 1] + bptr[1];
            v.z = acc[i * 8 + jj * 4 + 2] + bptr[2];
            v.w = acc[i * 8 + jj * 4 + 3] + bptr[3];
            if (EPI == 1) {
                float4 rv = *(const float4*)(rrow + jj * 4);
                v.x += rv.x; v.y += rv.y; v.z += rv.z; v.w += rv.w;
            }
            if (EPI == 2) {
                v.x = v.x * 0.5f * (1.0f + erff(v.x * 0.70710678118654752f));
                v.y = v.y * 0.5f * (1.0f + erff(v.y * 0.70710678118654752f));
                v.z = v.z * 0.5f * (1.0f + erff(v.z * 0.70710678118654752f));
                v.w = v.w * 0.5f * (1.0f + erff(v.w * 0.70710678118654752f));
            }
            *(float4*)(crow + jj * 4) = v;
        }
    }
}

// ---------------------------------------------------------------------------
// Flash attention (fp32, online softmax). 64x64 tiles, 256 threads.
// Additive -1e9 masks exactly mirror the reference's mask semantics.
// grid = (SEQ/64, NB*NHEAD)
// ---------------------------------------------------------------------------
__global__ void __launch_bounds__(256) flash_kernel(
    const float* __restrict__ Qg, const float* __restrict__ Kg,
    const float* __restrict__ Vg, const int* __restrict__ ids,
    float* __restrict__ Og, int causal)
{
    __shared__ float Qs [64 * 64];  // [d][row]  (scaled by 1/sqrt(dh))
    __shared__ float KPs[64 * 64];  // K as [d][col], reused as P [row][col]
    __shared__ float Vs [64 * 64];  // [col][d]

    const int tid = threadIdx.x;
    const int tx = tid & 15, ty = tid >> 4;
    const int qb = blockIdx.x;
    const int b  = blockIdx.y >> 4;
    const int h  = blockIdx.y & 15;
    const int i0 = qb * 64;

    const float* Qbase = Qg + (size_t)b * SEQ * D_MODEL + h * DHEAD;
    const float* Kbase = Kg + (size_t)b * SEQ * D_MODEL + h * DHEAD;
    const float* Vbase = Vg + (size_t)b * SEQ * D_MODEL + h * DHEAD;

    #pragma unroll
    for (int t = 0; t < 4; t++) {
        int lin = tid * 4 + t;
        int r = lin >> 4, d4 = lin & 15;
        float4 qv = *(const float4*)(Qbase + (size_t)(i0 + r) * D_MODEL + d4 * 4);
        Qs[(d4 * 4 + 0) * 64 + r] = qv.x * 0.125f;
        Qs[(d4 * 4 + 1) * 64 + r] = qv.y * 0.125f;
        Qs[(d4 * 4 + 2) * 64 + r] = qv.z * 0.125f;
        Qs[(d4 * 4 + 3) * 64 + r] = qv.w * 0.125f;
    }

    float o[16];
    #pragma unroll
    for (int i = 0; i < 16; i++) o[i] = 0.f;
    float m_i[4] = {-1e30f, -1e30f, -1e30f, -1e30f};
    float l_i[4] = {0.f, 0.f, 0.f, 0.f};

    const int nkb = causal ? (qb + 1) : (SEQ / 64);
    for (int kb = 0; kb < nkb; kb++) {
        __syncthreads();
        #pragma unroll
        for (int t = 0; t < 4; t++) {
            int lin = tid * 4 + t;
            int r = lin >> 4, d4 = lin & 15;
            float4 kv = *(const float4*)(Kbase + (size_t)(kb * 64 + r) * D_MODEL + d4 * 4);
            KPs[(d4 * 4 + 0) * 64 + r] = kv.x;
            KPs[(d4 * 4 + 1) * 64 + r] = kv.y;
            KPs[(d4 * 4 + 2) * 64 + r] = kv.z;
            KPs[(d4 * 4 + 3) * 64 + r] = kv.w;
            float4 vv = *(const float4*)(Vbase + (size_t)(kb * 64 + r) * D_MODEL + d4 * 4);
            *(float4*)(Vs + r * 64 + d4 * 4) = vv;
        }
        __syncthreads();

        float s[4][4];
        #pragma unroll
        for (int i = 0; i < 4; i++)
            #pragma unroll
            for (int j = 0; j < 4; j++) s[i][j] = 0.f;

        #pragma unroll 8
        for (int kk = 0; kk < 64; kk++) {
            float4 a  = *(const float4*)(Qs  + kk * 64 + ty * 4);
            float4 bb = *(const float4*)(KPs + kk * 64 + tx * 4);
            float av[4] = {a.x, a.y, a.z, a.w};
            float bv[4] = {bb.x, bb.y, bb.z, bb.w};
            #pragma unroll
            for (int i = 0; i < 4; i++)
                #pragma unroll
                for (int j = 0; j < 4; j++) s[i][j] += av[i] * bv[j];
        }

        // masks: pad (key token id == 0) and causal, additive like the reference
        #pragma unroll
        for (int j = 0; j < 4; j++) {
            int gj = kb * 64 + tx * 4 + j;
            float pm = (ids[b * SEQ + gj] == 0) ? NEGV : 0.f;
            #pragma unroll
            for (int i = 0; i < 4; i++) {
                float sv = s[i][j] + pm;
                if (causal && gj > (i0 + ty * 4 + i)) sv += NEGV;
                s[i][j] = sv;
            }
        }

        float alpha[4];
        #pragma unroll
        for (int i = 0; i < 4; i++) {
            float mx = fmaxf(fmaxf(s[i][0], s[i][1]), fmaxf(s[i][2], s[i][3]));
            #pragma unroll
            for (int off = 8; off > 0; off >>= 1)
                mx = fmaxf(mx, __shfl_xor_sync(0xffffffffu, mx, off, 16));
            float mn = fmaxf(m_i[i], mx);
            alpha[i] = __expf(m_i[i] - mn);
            m_i[i] = mn;
            float rs = 0.f;
            #pragma unroll
            for (int j = 0; j < 4; j++) { s[i][j] = __expf(s[i][j] - mn); rs += s[i][j]; }
            #pragma unroll
            for (int off = 8; off > 0; off >>= 1)
                rs += __shfl_xor_sync(0xffffffffu, rs, off, 16);
            l_i[i] = l_i[i] * alpha[i] + rs;
            #pragma unroll
            for (int c = 0; c < 4; c++) o[i * 4 + c] *= alpha[i];
        }

        __syncthreads();  // all S reads of KPs done before overwriting with P
        #pragma unroll
        for (int i = 0; i < 4; i++)
            *(float4*)(KPs + (ty * 4 + i) * 64 + tx * 4) =
                make_float4(s[i][0], s[i][1], s[i][2], s[i][3]);
        __syncthreads();

        #pragma unroll 4
        for (int j0 = 0; j0 < 64; j0 += 4) {
            float4 p0 = *(const float4*)(KPs + (ty * 4 + 0) * 64 + j0);
            float4 p1 = *(const float4*)(KPs + (ty * 4 + 1) * 64 + j0);
            float4 p2 = *(const float4*)(KPs + (ty * 4 + 2) * 64 + j0);
            float4 p3 = *(const float4*)(KPs + (ty * 4 + 3) * 64 + j0);
            float4 v0 = *(const float4*)(Vs + (j0 + 0) * 64 + tx * 4);
            float4 v1 = *(const float4*)(Vs + (j0 + 1) * 64 + tx * 4);
            float4 v2 = *(const float4*)(Vs + (j0 + 2) * 64 + tx * 4);
            float4 v3 = *(const float4*)(Vs + (j0 + 3) * 64 + tx * 4);
            float pr[4][4] = {{p0.x, p0.y, p0.z, p0.w}, {p1.x, p1.y, p1.z, p1.w},
                              {p2.x, p2.y, p2.z, p2.w}, {p3.x, p3.y, p3.z, p3.w}};
            float vr[4][4] = {{v0.x, v0.y, v0.z, v0.w}, {v1.x, v1.y, v1.z, v1.w},
                              {v2.x, v2.y, v2.z, v2.w}, {v3.x, v3.y, v3.z, v3.w}};
            #pragma unroll
            for (int i = 0; i < 4; i++)
                #pragma unroll
                for (int c = 0; c < 4; c++)
                    o[i * 4 + c] += pr[i][0] * vr[0][c] + pr[i][1] * vr[1][c]
                                  + pr[i][2] * vr[2][c] + pr[i][3] * vr[3][c];
        }
    }

    #pragma unroll
    for (int i = 0; i < 4; i++) {
        float inv = 1.f / l_i[i];
        float4 ov = make_float4(o[i * 4 + 0] * inv, o[i * 4 + 1] * inv,
                                o[i * 4 + 2] * inv, o[i * 4 + 3] * inv);
        *(float4*)(Og + (size_t)(b * SEQ + i0 + ty * 4 + i) * D_MODEL
                   + h * DHEAD + tx * 4) = ov;
    }
}

// ---------------------------------------------------------------------------
// Launch
// ---------------------------------------------------------------------------
extern "C" void kernel_launch(void* const* d_in, const int* in_sizes, int n_in,
                              void* d_out, int out_size)
{
    (void)in_sizes; (void)n_in; (void)out_size;

    const float* input_embedding = (const float*)d_in[0];
    const int*   input_ids       = (const int*)  d_in[1];
    const int*   target_ids      = (const int*)  d_in[2];
    const float* tok_emb         = (const float*)d_in[3];
    const float* pos_emb         = (const float*)d_in[4];
    const float* ln1_g = (const float*)d_in[5];
    const float* ln1_b = (const float*)d_in[6];
    const float* q1_w  = (const float*)d_in[7];
    const float* q1_b  = (const float*)d_in[8];
    const float* k1_w  = (const float*)d_in[9];
    const float* k1_b  = (const float*)d_in[10];
    const float* v1_w  = (const float*)d_in[11];
    const float* v1_b  = (const float*)d_in[12];
    const float* out1_w = (const float*)d_in[13];
    const float* out1_b = (const float*)d_in[14];
    const float* ln2_g = (const float*)d_in[15];
    const float* ln2_b = (const float*)d_in[16];
    const float* q2_w  = (const float*)d_in[17];
    const float* q2_b  = (const float*)d_in[18];
    const float* k2_w  = (const float*)d_in[19];
    const float* k2_b  = (const float*)d_in[20];
    const float* v2_w  = (const float*)d_in[21];
    const float* v2_b  = (const float*)d_in[22];
    const float* out2_w = (const float*)d_in[23];
    const float* out2_b = (const float*)d_in[24];
    const float* ln3_g = (const float*)d_in[25];
    const float* ln3_b = (const float*)d_in[26];
    const float* mlp_w1 = (const float*)d_in[27];
    const float* mlp_b1 = (const float*)d_in[28];
    const float* mlp_w2 = (const float*)d_in[29];
    const float* mlp_b2 = (const float*)d_in[30];

    float *x, *q, *k, *v, *attn, *h, *hln, *r, *z, *mh;
    cudaGetSymbolAddress((void**)&x,    g_x);
    cudaGetSymbolAddress((void**)&q,    g_q);
    cudaGetSymbolAddress((void**)&k,    g_k);
    cudaGetSymbolAddress((void**)&v,    g_v);
    cudaGetSymbolAddress((void**)&attn, g_attn);
    cudaGetSymbolAddress((void**)&h,    g_h);
    cudaGetSymbolAddress((void**)&hln,  g_hln);
    cudaGetSymbolAddress((void**)&r,    g_r);
    cudaGetSymbolAddress((void**)&z,    g_z);
    cudaGetSymbolAddress((void**)&mh,   g_mh);

    float* out = (float*)d_out;

    dim3 gN1024(1024 / 128, NTOK / 128);   // (8, 32)
    dim3 gN4096(4096 / 128, NTOK / 128);   // (32, 32)
    dim3 gAttn(SEQ / 64, NB * NHEAD);      // (32, 32)

    // x = LN1(tok_emb[target_ids] + pos_emb)
    embed_ln_kernel<<<NTOK, 256>>>(target_ids, tok_emb, pos_emb, ln1_g, ln1_b, x);

    // self-attention QKV
    gemm_kernel<0><<<gN1024, 256>>>(x, q1_w, q1_b, nullptr, q, NTOK, 1024, 1024);
    gemm_kernel<0><<<gN1024, 256>>>(x, k1_w, k1_b, nullptr, k, NTOK, 1024, 1024);
    gemm_kernel<0><<<gN1024, 256>>>(x, v1_w, v1_b, nullptr, v, NTOK, 1024, 1024);
    flash_kernel<<<gAttn, 256>>>(q, k, v, target_ids, attn, 1);

    // h = x + attn @ out1_w + out1_b ; hln = LN2(h)
    gemm_kernel<1><<<gN1024, 256>>>(attn, out1_w, out1_b, x, h, NTOK, 1024, 1024);
    ln_kernel<<<NTOK, 256>>>(h, ln2_g, ln2_b, hln);

    // cross-attention: Q from hln, K/V from input_embedding
    gemm_kernel<0><<<gN1024, 256>>>(hln,             q2_w, q2_b, nullptr, q, NTOK, 1024, 1024);
    gemm_kernel<0><<<gN1024, 256>>>(input_embedding, k2_w, k2_b, nullptr, k, NTOK, 1024, 1024);
    gemm_kernel<0><<<gN1024, 256>>>(input_embedding, v2_w, v2_b, nullptr, v, NTOK, 1024, 1024);
    flash_kernel<<<gAttn, 256>>>(q, k, v, input_ids, attn, 0);

    // r = hln + cross @ out2_w + out2_b  (residual is the POST-LN2 tensor)
    gemm_kernel<1><<<gN1024, 256>>>(attn, out2_w, out2_b, hln, r, NTOK, 1024, 1024);

    // z = LN3(r); MLP with exact GELU; out = mlp + r
    ln_kernel<<<NTOK, 256>>>(r, ln3_g, ln3_b, z);
    gemm_kernel<2><<<gN4096, 256>>>(z,  mlp_w1, mlp_b1, nullptr, mh, NTOK, 4096, 1024);
    gemm_kernel<1><<<gN1024, 256>>>(mh, mlp_w2, mlp_b2, r, out, NTOK, 1024, 4096);
}

// round 4
// speedup vs baseline: 1.6282x; 1.6282x over previous
#include <cuda_runtime.h>
#include <cuda_bf16.h>
#include <math.h>
#include <stdint.h>

#define D_MODEL 1024
#define SEQ     2048
#define NB      2
#define NTOK    (NB * SEQ)      // 4096 tokens
#define NHEAD   16
#define DHEAD   64
#define NEGV    (-1000000000.0f)

// ---------------------------------------------------------------------------
// Scratch buffers (static __device__ — no allocation allowed)
// ---------------------------------------------------------------------------
__device__ float g_x   [NTOK * D_MODEL];
__device__ float g_q   [NTOK * D_MODEL];
__device__ float g_k   [NTOK * D_MODEL];
__device__ float g_v   [NTOK * D_MODEL];
__device__ float g_attn[NTOK * D_MODEL];
__device__ float g_h   [NTOK * D_MODEL];
__device__ float g_hln [NTOK * D_MODEL];
__device__ float g_r   [NTOK * D_MODEL];
__device__ float g_z   [NTOK * D_MODEL];
__device__ float g_mh  [(size_t)NTOK * 4096];

// bf16 hi/lo splits: activations and weights
__device__ __nv_bfloat16 g_aH[(size_t)NTOK * 4096];
__device__ __nv_bfloat16 g_aL[(size_t)NTOK * 4096];
__device__ __nv_bfloat16 g_bH[(size_t)4096 * 1024];
__device__ __nv_bfloat16 g_bL[(size_t)4096 * 1024];

// ---------------------------------------------------------------------------
// PTX helpers (all arch-agnostic: ldmatrix sm_75+, mma bf16 sm_80+, cp.async sm_80+)
// ---------------------------------------------------------------------------
__device__ __forceinline__ uint32_t smem_u32(const void* p) {
    uint32_t a;
    asm("{ .reg .u64 t; cvta.to.shared.u64 t, %1; cvt.u32.u64 %0, t; }" : "=r"(a) : "l"(p));
    return a;
}
#define CP_ASYNC16(dst, src) \
    asm volatile("cp.async.cg.shared.global [%0], [%1], 16;" :: "r"(dst), "l"(src) : "memory")
#define CP_COMMIT() asm volatile("cp.async.commit_group;" ::: "memory")
#define CP_WAIT0()  asm volatile("cp.async.wait_group 0;" ::: "memory")
#define CP_WAIT1()  asm volatile("cp.async.wait_group 1;" ::: "memory")

__device__ __forceinline__ void ldsm_x4(uint32_t* r, uint32_t addr) {
    asm volatile("ldmatrix.sync.aligned.m8n8.x4.shared.b16 {%0,%1,%2,%3}, [%4];"
                 : "=r"(r[0]), "=r"(r[1]), "=r"(r[2]), "=r"(r[3]) : "r"(addr));
}
__device__ __forceinline__ void ldsm_x2t(uint32_t* r, uint32_t addr) {
    asm volatile("ldmatrix.sync.aligned.m8n8.x2.trans.shared.b16 {%0,%1}, [%2];"
                 : "=r"(r[0]), "=r"(r[1]) : "r"(addr));
}
__device__ __forceinline__ void mma_bf16(float* c, const uint32_t* a, const uint32_t* b) {
    asm volatile("mma.sync.aligned.m16n8k16.row.col.f32.bf16.bf16.f32 "
                 "{%0,%1,%2,%3}, {%4,%5,%6,%7}, {%8,%9}, {%0,%1,%2,%3};"
                 : "+f"(c[0]), "+f"(c[1]), "+f"(c[2]), "+f"(c[3])
                 : "r"(a[0]), "r"(a[1]), "r"(a[2]), "r"(a[3]), "r"(b[0]), "r"(b[1]));
}

// ---------------------------------------------------------------------------
// HMMA GEMM: C[M,N] = A[M,K] @ W[K,N] (+bias, +epi) via 3xbf16 compensation.
// A hi/lo: [M,K] row-major. W hi/lo: [K,N] row-major (no transpose needed —
// B fragments loaded with ldmatrix.trans).
// CTA tile 128x128, 8 warps of 64m x 32n, BK=64, cp.async double buffer.
// ---------------------------------------------------------------------------
#define SA_H 0
#define SA_L 18432           // 128 rows * 144 B (72 bf16, padded)
#define SB_H 36864
#define SB_L 54272           // 64 rows * 272 B (136 bf16, padded)
#define STAGE 71680
#define GEMM_SMEM (2 * STAGE)   // 143360 B

__device__ __forceinline__ void issue_chunk(uint32_t sb,
    const __nv_bfloat16* __restrict__ Ah, const __nv_bfloat16* __restrict__ Al,
    const __nv_bfloat16* __restrict__ Bh, const __nv_bfloat16* __restrict__ Bl,
    size_t row0, size_t col0, int K, int N, int k0, int tid)
{
    #pragma unroll
    for (int i = 0; i < 4; i++) {
        int idx = i * 256 + tid;           // 0..1023
        int r   = idx >> 3;                // 0..127
        int c8  = (idx & 7) * 8;           // 0..56
        uint32_t so = sb + (uint32_t)(r * 144 + c8 * 2);
        size_t   go = (row0 + r) * (size_t)K + k0 + c8;
        CP_ASYNC16(so + SA_H, Ah + go);
        CP_ASYNC16(so + SA_L, Al + go);
    }
    #pragma unroll
    for (int i = 0; i < 4; i++) {
        int idx = i * 256 + tid;
        int r   = idx >> 4;                // 0..63
        int c8  = (idx & 15) * 8;          // 0..120
        uint32_t so = sb + (uint32_t)(r * 272 + c8 * 2);
        size_t   go = (size_t)(k0 + r) * N + col0 + c8;
        CP_ASYNC16(so + SB_H, Bh + go);
        CP_ASYNC16(so + SB_L, Bl + go);
    }
}

template <int EPI>  // 0 = bias, 1 = bias+residual, 2 = bias+exact GELU
__global__ void __launch_bounds__(256, 1) gemm_mma_kernel(
    const __nv_bfloat16* __restrict__ Ah, const __nv_bfloat16* __restrict__ Al,
    const __nv_bfloat16* __restrict__ Bh, const __nv_bfloat16* __restrict__ Bl,
    const float* __restrict__ bias, const float* __restrict__ res,
    float* __restrict__ C, int N, int K)
{
    extern __shared__ char smem[];
    const uint32_t sbase = smem_u32(smem);
    const int tid  = threadIdx.x;
    const int wid  = tid >> 5;
    const int lane = tid & 31;
    const int wm   = wid >> 2;             // 0..1  (64-row slab)
    const int wn   = wid & 3;              // 0..3  (32-col slab)
    const size_t row0 = (size_t)blockIdx.y * 128;
    const size_t col0 = (size_t)blockIdx.x * 128;

    float acc[4][4][4];
    #pragma unroll
    for (int i = 0; i < 4; i++)
        #pragma unroll
        for (int j = 0; j < 4; j++)
            #pragma unroll
            for (int c = 0; c < 4; c++) acc[i][j][c] = 0.f;

    const int nch = K >> 6;
    issue_chunk(sbase, Ah, Al, Bh, Bl, row0, col0, K, N, 0, tid);
    CP_COMMIT();

    // per-lane fragment address components (element offsets precomputed)
    const int aRow = (lane & 15);                    // m within 16
    const int aColB = ((lane >> 4) << 3) * 2;        // k byte offset within 16
    const int l16  = lane & 15;
    const int bRow = (l16 & 7) + ((l16 >> 3) & 1) * 8;   // k within 16

    for (int ch = 0; ch < nch; ch++) {
        if (ch + 1 < nch) {
            issue_chunk(sbase + ((ch + 1) & 1) * STAGE, Ah, Al, Bh, Bl,
                        row0, col0, K, N, (ch + 1) << 6, tid);
            CP_COMMIT();
            CP_WAIT1();
        } else {
            CP_WAIT0();
        }
        __syncthreads();

        const uint32_t st = sbase + (ch & 1) * STAGE;
        #pragma unroll
        for (int kk = 0; kk < 64; kk += 16) {
            uint32_t ah[4][4], al[4][4], bh[4][2], bl[4][2];
            #pragma unroll
            for (int mi = 0; mi < 4; mi++) {
                uint32_t ao = st + (uint32_t)((wm * 64 + mi * 16 + aRow) * 144 + kk * 2 + aColB);
                ldsm_x4(ah[mi], ao + SA_H);
                ldsm_x4(al[mi], ao + SA_L);
            }
            #pragma unroll
            for (int ni = 0; ni < 4; ni++) {
                uint32_t bo = st + (uint32_t)((kk + bRow) * 272 + (wn * 32 + ni * 8) * 2);
                ldsm_x2t(bh[ni], bo + SB_H);
                ldsm_x2t(bl[ni], bo + SB_L);
            }
            #pragma unroll
            for (int mi = 0; mi < 4; mi++)
                #pragma unroll
                for (int ni = 0; ni < 4; ni++) {
                    mma_bf16(acc[mi][ni], ah[mi], bh[ni]);
                    mma_bf16(acc[mi][ni], ah[mi], bl[ni]);
                    mma_bf16(acc[mi][ni], al[mi], bh[ni]);
                }
        }
        __syncthreads();
    }

    // epilogue: c0,c1 -> row (lane>>2), cols 2*(lane&3); c2,c3 -> row+8
    #pragma unroll
    for (int mi = 0; mi < 4; mi++) {
        #pragma unroll
        for (int ni = 0; ni < 4; ni++) {
            int m  = wm * 64 + mi * 16 + (lane >> 2);
            size_t gc = col0 + wn * 32 + ni * 8 + (lane & 3) * 2;
            float b0 = bias[gc], b1 = bias[gc + 1];
            #pragma unroll
            for (int half = 0; half < 2; half++) {
                size_t gr = row0 + m + half * 8;
                float vx = acc[mi][ni][half * 2 + 0] + b0;
                float vy = acc[mi][ni][half * 2 + 1] + b1;
                if (EPI == 1) {
                    float2 rv = *(const float2*)(res + gr * (size_t)N + gc);
                    vx += rv.x; vy += rv.y;
                }
                if (EPI == 2) {
                    vx = vx * 0.5f * (1.0f + erff(vx * 0.70710678118654752f));
                    vy = vy * 0.5f * (1.0f + erff(vy * 0.70710678118654752f));
                }
                float2 o = make_float2(vx, vy);
                *(float2*)(C + gr * (size_t)N + gc) = o;
            }
        }
    }
}

// ---------------------------------------------------------------------------
// Split fp32 -> bf16 hi/lo (elementwise); used for activations AND weights
// ---------------------------------------------------------------------------
__global__ void __launch_bounds__(256) conva_kernel(
    const float* __restrict__ X, __nv_bfloat16* __restrict__ hi,
    __nv_bfloat16* __restrict__ lo)
{
    size_t i = ((size_t)blockIdx.x * 256 + threadIdx.x) * 4;
    float4 v = *(const float4*)(X + i);
    __nv_bfloat16 h0 = __float2bfloat16(v.x), h1 = __float2bfloat16(v.y);
    __nv_bfloat16 h2 = __float2bfloat16(v.z), h3 = __float2bfloat16(v.w);
    __nv_bfloat16 l0 = __float2bfloat16(v.x - __bfloat162float(h0));
    __nv_bfloat16 l1 = __float2bfloat16(v.y - __bfloat162float(h1));
    __nv_bfloat16 l2 = __float2bfloat16(v.z - __bfloat162float(h2));
    __nv_bfloat16 l3 = __float2bfloat16(v.w - __bfloat162float(h3));
    *(__nv_bfloat162*)(hi + i)     = __nv_bfloat162(h0, h1);
    *(__nv_bfloat162*)(hi + i + 2) = __nv_bfloat162(h2, h3);
    *(__nv_bfloat162*)(lo + i)     = __nv_bfloat162(l0, l1);
    *(__nv_bfloat162*)(lo + i + 2) = __nv_bfloat162(l2, l3);
}

// ---------------------------------------------------------------------------
// Block reduce / LayerNorm / embed
// ---------------------------------------------------------------------------
__device__ __forceinline__ float2 block_reduce_sum2(float a, float b) {
    #pragma unroll
    for (int o = 16; o > 0; o >>= 1) {
        a += __shfl_xor_sync(0xffffffffu, a, o);
        b += __shfl_xor_sync(0xffffffffu, b, o);
    }
    __shared__ float sa[8], sb[8];
    int w = threadIdx.x >> 5;
    if ((threadIdx.x & 31) == 0) { sa[w] = a; sb[w] = b; }
    __syncthreads();
    float ta = 0.f, tb = 0.f;
    #pragma unroll
    for (int k = 0; k < 8; k++) { ta += sa[k]; tb += sb[k]; }
    return make_float2(ta, tb);
}

__global__ void __launch_bounds__(256) embed_ln_kernel(
    const int* __restrict__ ids, const float* __restrict__ tok,
    const float* __restrict__ pos, const float* __restrict__ g,
    const float* __restrict__ be, float* __restrict__ out)
{
    int row = blockIdx.x;
    int s   = row & (SEQ - 1);
    int id  = ids[row];
    int i   = threadIdx.x;
    float4 tv = ((const float4*)(tok + (size_t)id * D_MODEL))[i];
    float4 pv = ((const float4*)(pos + (size_t)s  * D_MODEL))[i];
    float4 v  = make_float4(tv.x + pv.x, tv.y + pv.y, tv.z + pv.z, tv.w + pv.w);
    float2 ss = block_reduce_sum2(v.x + v.y + v.z + v.w,
                                  v.x*v.x + v.y*v.y + v.z*v.z + v.w*v.w);
    float mean = ss.x * (1.f / D_MODEL);
    float var  = ss.y * (1.f / D_MODEL) - mean * mean;
    float rstd = rsqrtf(var + 1e-5f);
    float4 gv = ((const float4*)g)[i];
    float4 bv = ((const float4*)be)[i];
    float4 o  = make_float4((v.x - mean) * rstd * gv.x + bv.x,
                            (v.y - mean) * rstd * gv.y + bv.y,
                            (v.z - mean) * rstd * gv.z + bv.z,
                            (v.w - mean) * rstd * gv.w + bv.w);
    ((float4*)(out + (size_t)row * D_MODEL))[i] = o;
}

__global__ void __launch_bounds__(256) ln_kernel(
    const float* __restrict__ in, const float* __restrict__ g,
    const float* __restrict__ be, float* __restrict__ out)
{
    int row = blockIdx.x;
    int i   = threadIdx.x;
    float4 v = ((const float4*)(in + (size_t)row * D_MODEL))[i];
    float2 ss = block_reduce_sum2(v.x + v.y + v.z + v.w,
                                  v.x*v.x + v.y*v.y + v.z*v.z + v.w*v.w);
    float mean = ss.x * (1.f / D_MODEL);
    float var  = ss.y * (1.f / D_MODEL) - mean * mean;
    float rstd = rsqrtf(var + 1e-5f);
    float4 gv = ((const float4*)g)[i];
    float4 bv = ((const float4*)be)[i];
    float4 o  = make_float4((v.x - mean) * rstd * gv.x + bv.x,
                            (v.y - mean) * rstd * gv.y + bv.y,
                            (v.z - mean) * rstd * gv.z + bv.z,
                            (v.w - mean) * rstd * gv.w + bv.w);
    ((float4*)(out + (size_t)row * D_MODEL))[i] = o;
}

// ---------------------------------------------------------------------------
// Flash attention (fp32, online softmax) — unchanged from passing round
// ---------------------------------------------------------------------------
__global__ void __launch_bounds__(256) flash_kernel(
    const float* __restrict__ Qg, const float* __restrict__ Kg,
    const float* __restrict__ Vg, const int* __restrict__ ids,
    float* __restrict__ Og, int causal)
{
    __shared__ float Qs [64 * 64];
    __shared__ float KPs[64 * 64];
    __shared__ float Vs [64 * 64];

    const int tid = threadIdx.x;
    const int tx = tid & 15, ty = tid >> 4;
    const int qb = blockIdx.x;
    const int b  = blockIdx.y >> 4;
    const int h  = blockIdx.y & 15;
    const int i0 = qb * 64;

    const float* Qbase = Qg + (size_t)b * SEQ * D_MODEL + h * DHEAD;
    const float* Kbase = Kg + (size_t)b * SEQ * D_MODEL + h * DHEAD;
    const float* Vbase = Vg + (size_t)b * SEQ * D_MODEL + h * DHEAD;

    #pragma unroll
    for (int t = 0; t < 4; t++) {
        int lin = tid * 4 + t;
        int r = lin >> 4, d4 = lin & 15;
        float4 qv = *(const float4*)(Qbase + (size_t)(i0 + r) * D_MODEL + d4 * 4);
        Qs[(d4 * 4 + 0) * 64 + r] = qv.x * 0.125f;
        Qs[(d4 * 4 + 1) * 64 + r] = qv.y * 0.125f;
        Qs[(d4 * 4 + 2) * 64 + r] = qv.z * 0.125f;
        Qs[(d4 * 4 + 3) * 64 + r] = qv.w * 0.125f;
    }

    float o[16];
    #pragma unroll
    for (int i = 0; i < 16; i++) o[i] = 0.f;
    float m_i[4] = {-1e30f, -1e30f, -1e30f, -1e30f};
    float l_i[4] = {0.f, 0.f, 0.f, 0.f};

    const int nkb = causal ? (qb + 1) : (SEQ / 64);
    for (int kb = 0; kb < nkb; kb++) {
        __syncthreads();
        #pragma unroll
        for (int t = 0; t < 4; t++) {
            int lin = tid * 4 + t;
            int r = lin >> 4, d4 = lin & 15;
            float4 kv = *(const float4*)(Kbase + (size_t)(kb * 64 + r) * D_MODEL + d4 * 4);
            KPs[(d4 * 4 + 0) * 64 + r] = kv.x;
            KPs[(d4 * 4 + 1) * 64 + r] = kv.y;
            KPs[(d4 * 4 + 2) * 64 + r] = kv.z;
            KPs[(d4 * 4 + 3) * 64 + r] = kv.w;
            float4 vv = *(const float4*)(Vbase + (size_t)(kb * 64 + r) * D_MODEL + d4 * 4);
            *(float4*)(Vs + r * 64 + d4 * 4) = vv;
        }
        __syncthreads();

        float s[4][4];
        #pragma unroll
        for (int i = 0; i < 4; i++)
            #pragma unroll
            for (int j = 0; j < 4; j++) s[i][j] = 0.f;

        #pragma unroll 8
        for (int kk = 0; kk < 64; kk++) {
            float4 a  = *(const float4*)(Qs  + kk * 64 + ty * 4);
            float4 bb = *(const float4*)(KPs + kk * 64 + tx * 4);
            float av[4] = {a.x, a.y, a.z, a.w};
            float bv[4] = {bb.x, bb.y, bb.z, bb.w};
            #pragma unroll
            for (int i = 0; i < 4; i++)
                #pragma unroll
                for (int j = 0; j < 4; j++) s[i][j] += av[i] * bv[j];
        }

        #pragma unroll
        for (int j = 0; j < 4; j++) {
            int gj = kb * 64 + tx * 4 + j;
            float pm = (ids[b * SEQ + gj] == 0) ? NEGV : 0.f;
            #pragma unroll
            for (int i = 0; i < 4; i++) {
                float sv = s[i][j] + pm;
                if (causal && gj > (i0 + ty * 4 + i)) sv += NEGV;
                s[i][j] = sv;
            }
        }

        float alpha[4];
        #pragma unroll
        for (int i = 0; i < 4; i++) {
            float mx = fmaxf(fmaxf(s[i][0], s[i][1]), fmaxf(s[i][2], s[i][3]));
            #pragma unroll
            for (int off = 8; off > 0; off >>= 1)
                mx = fmaxf(mx, __shfl_xor_sync(0xffffffffu, mx, off, 16));
            float mn = fmaxf(m_i[i], mx);
            alpha[i] = __expf(m_i[i] - mn);
            m_i[i] = mn;
            float rs = 0.f;
            #pragma unroll
            for (int j = 0; j < 4; j++) { s[i][j] = __expf(s[i][j] - mn); rs += s[i][j]; }
            #pragma unroll
            for (int off = 8; off > 0; off >>= 1)
                rs += __shfl_xor_sync(0xffffffffu, rs, off, 16);
            l_i[i] = l_i[i] * alpha[i] + rs;
            #pragma unroll
            for (int c = 0; c < 4; c++) o[i * 4 + c] *= alpha[i];
        }

        __syncthreads();
        #pragma unroll
        for (int i = 0; i < 4; i++)
            *(float4*)(KPs + (ty * 4 + i) * 64 + tx * 4) =
                make_float4(s[i][0], s[i][1], s[i][2], s[i][3]);
        __syncthreads();

        #pragma unroll 4
        for (int j0 = 0; j0 < 64; j0 += 4) {
            float4 p0 = *(const float4*)(KPs + (ty * 4 + 0) * 64 + j0);
            float4 p1 = *(const float4*)(KPs + (ty * 4 + 1) * 64 + j0);
            float4 p2 = *(const float4*)(KPs + (ty * 4 + 2) * 64 + j0);
            float4 p3 = *(const float4*)(KPs + (ty * 4 + 3) * 64 + j0);
            float4 v0 = *(const float4*)(Vs + (j0 + 0) * 64 + tx * 4);
            float4 v1 = *(const float4*)(Vs + (j0 + 1) * 64 + tx * 4);
            float4 v2 = *(const float4*)(Vs + (j0 + 2) * 64 + tx * 4);
            float4 v3 = *(const float4*)(Vs + (j0 + 3) * 64 + tx * 4);
            float pr[4][4] = {{p0.x, p0.y, p0.z, p0.w}, {p1.x, p1.y, p1.z, p1.w},
                              {p2.x, p2.y, p2.z, p2.w}, {p3.x, p3.y, p3.z, p3.w}};
            float vr[4][4] = {{v0.x, v0.y, v0.z, v0.w}, {v1.x, v1.y, v1.z, v1.w},
                              {v2.x, v2.y, v2.z, v2.w}, {v3.x, v3.y, v3.z, v3.w}};
            #pragma unroll
            for (int i = 0; i < 4; i++)
                #pragma unroll
                for (int c = 0; c < 4; c++)
                    o[i * 4 + c] += pr[i][0] * vr[0][c] + pr[i][1] * vr[1][c]
                                  + pr[i][2] * vr[2][c] + pr[i][3] * vr[3][c];
        }
    }

    #pragma unroll
    for (int i = 0; i < 4; i++) {
        float inv = 1.f / l_i[i];
        float4 ov = make_float4(o[i * 4 + 0] * inv, o[i * 4 + 1] * inv,
                                o[i * 4 + 2] * inv, o[i * 4 + 3] * inv);
        *(float4*)(Og + (size_t)(b * SEQ + i0 + ty * 4 + i) * D_MODEL
                   + h * DHEAD + tx * 4) = ov;
    }
}

// ---------------------------------------------------------------------------
// Launch
// ---------------------------------------------------------------------------
extern "C" void kernel_launch(void* const* d_in, const int* in_sizes, int n_in,
                              void* d_out, int out_size)
{
    (void)in_sizes; (void)n_in; (void)out_size;

    const float* input_embedding = (const float*)d_in[0];
    const int*   input_ids       = (const int*)  d_in[1];
    const int*   target_ids      = (const int*)  d_in[2];
    const float* tok_emb         = (const float*)d_in[3];
    const float* pos_emb         = (const float*)d_in[4];
    const float* ln1_g = (const float*)d_in[5];
    const float* ln1_b = (const float*)d_in[6];
    const float* q1_w  = (const float*)d_in[7];
    const float* q1_b  = (const float*)d_in[8];
    const float* k1_w  = (const float*)d_in[9];
    const float* k1_b  = (const float*)d_in[10];
    const float* v1_w  = (const float*)d_in[11];
    const float* v1_b  = (const float*)d_in[12];
    const float* out1_w = (const float*)d_in[13];
    const float* out1_b = (const float*)d_in[14];
    const float* ln2_g = (const float*)d_in[15];
    const float* ln2_b = (const float*)d_in[16];
    const float* q2_w  = (const float*)d_in[17];
    const float* q2_b  = (const float*)d_in[18];
    const float* k2_w  = (const float*)d_in[19];
    const float* k2_b  = (const float*)d_in[20];
    const float* v2_w  = (const float*)d_in[21];
    const float* v2_b  = (const float*)d_in[22];
    const float* out2_w = (const float*)d_in[23];
    const float* out2_b = (const float*)d_in[24];
    const float* ln3_g = (const float*)d_in[25];
    const float* ln3_b = (const float*)d_in[26];
    const float* mlp_w1 = (const float*)d_in[27];
    const float* mlp_b1 = (const float*)d_in[28];
    const float* mlp_w2 = (const float*)d_in[29];
    const float* mlp_b2 = (const float*)d_in[30];

    float *x, *q, *k, *v, *attn, *h, *hln, *r, *z, *mh;
    __nv_bfloat16 *aH, *aL, *bH, *bL;
    cudaGetSymbolAddress((void**)&x,    g_x);
    cudaGetSymbolAddress((void**)&q,    g_q);
    cudaGetSymbolAddress((void**)&k,    g_k);
    cudaGetSymbolAddress((void**)&v,    g_v);
    cudaGetSymbolAddress((void**)&attn, g_attn);
    cudaGetSymbolAddress((void**)&h,    g_h);
    cudaGetSymbolAddress((void**)&hln,  g_hln);
    cudaGetSymbolAddress((void**)&r,    g_r);
    cudaGetSymbolAddress((void**)&z,    g_z);
    cudaGetSymbolAddress((void**)&mh,   g_mh);
    cudaGetSymbolAddress((void**)&aH,   g_aH);
    cudaGetSymbolAddress((void**)&aL,   g_aL);
    cudaGetSymbolAddress((void**)&bH,   g_bH);
    cudaGetSymbolAddress((void**)&bL,   g_bL);

    float* out = (float*)d_out;

    cudaFuncSetAttribute(gemm_mma_kernel<0>, cudaFuncAttributeMaxDynamicSharedMemorySize, GEMM_SMEM);
    cudaFuncSetAttribute(gemm_mma_kernel<1>, cudaFuncAttributeMaxDynamicSharedMemorySize, GEMM_SMEM);
    cudaFuncSetAttribute(gemm_mma_kernel<2>, cudaFuncAttributeMaxDynamicSharedMemorySize, GEMM_SMEM);

    const dim3 gN1024(1024 / 128, NTOK / 128);   // (8, 32)
    const dim3 gN4096(4096 / 128, NTOK / 128);   // (32, 32)
    const dim3 gAttn(SEQ / 64, NB * NHEAD);
    const int  cAct1024 = (NTOK * 1024) / 1024;
    const int  cAct4096 = (NTOK * 4096) / 1024;
    const int  cW1M = (1024 * 1024) / 1024;
    const int  cW4M = (4096 * 1024) / 1024;

    // x = LN1(embed)
    embed_ln_kernel<<<NTOK, 256>>>(target_ids, tok_emb, pos_emb, ln1_g, ln1_b, x);

    // ---- self attention ----
    conva_kernel<<<cAct1024, 256>>>(x, aH, aL);
    conva_kernel<<<cW1M, 256>>>(q1_w, bH, bL);
    gemm_mma_kernel<0><<<gN1024, 256, GEMM_SMEM>>>(aH, aL, bH, bL, q1_b, nullptr, q, 1024, 1024);
    conva_kernel<<<cW1M, 256>>>(k1_w, bH, bL);
    gemm_mma_kernel<0><<<gN1024, 256, GEMM_SMEM>>>(aH, aL, bH, bL, k1_b, nullptr, k, 1024, 1024);
    conva_kernel<<<cW1M, 256>>>(v1_w, bH, bL);
    gemm_mma_kernel<0><<<gN1024, 256, GEMM_SMEM>>>(aH, aL, bH, bL, v1_b, nullptr, v, 1024, 1024);
    flash_kernel<<<gAttn, 256>>>(q, k, v, target_ids, attn, 1);

    conva_kernel<<<cAct1024, 256>>>(attn, aH, aL);
    conva_kernel<<<cW1M, 256>>>(out1_w, bH, bL);
    gemm_mma_kernel<1><<<gN1024, 256, GEMM_SMEM>>>(aH, aL, bH, bL, out1_b, x, h, 1024, 1024);
    ln_kernel<<<NTOK, 256>>>(h, ln2_g, ln2_b, hln);

    // ---- cross attention ----
    conva_kernel<<<cAct1024, 256>>>(hln, aH, aL);
    conva_kernel<<<cW1M, 256>>>(q2_w, bH, bL);
    gemm_mma_kernel<0><<<gN1024, 256, GEMM_SMEM>>>(aH, aL, bH, bL, q2_b, nullptr, q, 1024, 1024);
    conva_kernel<<<cAct1024, 256>>>(input_embedding, aH, aL);
    conva_kernel<<<cW1M, 256>>>(k2_w, bH, bL);
    gemm_mma_kernel<0><<<gN1024, 256, GEMM_SMEM>>>(aH, aL, bH, bL, k2_b, nullptr, k, 1024, 1024);
    conva_kernel<<<cW1M, 256>>>(v2_w, bH, bL);
    gemm_mma_kernel<0><<<gN1024, 256, GEMM_SMEM>>>(aH, aL, bH, bL, v2_b, nullptr, v, 1024, 1024);
    flash_kernel<<<gAttn, 256>>>(q, k, v, input_ids, attn, 0);

    conva_kernel<<<cAct1024, 256>>>(attn, aH, aL);
    conva_kernel<<<cW1M, 256>>>(out2_w, bH, bL);
    gemm_mma_kernel<1><<<gN1024, 256, GEMM_SMEM>>>(aH, aL, bH, bL, out2_b, hln, r, 1024, 1024);

    // ---- MLP ----
    ln_kernel<<<NTOK, 256>>>(r, ln3_g, ln3_b, z);
    conva_kernel<<<cAct1024, 256>>>(z, aH, aL);
    conva_kernel<<<cW4M, 256>>>(mlp_w1, bH, bL);
    gemm_mma_kernel<2><<<gN4096, 256, GEMM_SMEM>>>(aH, aL, bH, bL, mlp_b1, nullptr, mh, 4096, 1024);
    conva_kernel<<<cAct4096, 256>>>(mh, aH, aL);
    conva_kernel<<<cW4M, 256>>>(mlp_w2, bH, bL);
    gemm_mma_kernel<1><<<gN1024, 256, GEMM_SMEM>>>(aH, aL, bH, bL, mlp_b2, r, out, 1024, 4096);
}

// round 5
// speedup vs baseline: 2.7437x; 1.6851x over previous
#include <cuda_runtime.h>
#include <cuda_bf16.h>
#include <cuda_fp16.h>
#include <math.h>
#include <stdint.h>

#define D_MODEL 1024
#define SEQ     2048
#define NB      2
#define NTOK    (NB * SEQ)      // 4096 tokens
#define NHEAD   16
#define DHEAD   64
#define NEGV    (-1000000000.0f)

// ---------------------------------------------------------------------------
// Scratch buffers (static __device__ — no allocation allowed)
// ---------------------------------------------------------------------------
__device__ float g_x   [NTOK * D_MODEL];
__device__ float g_q   [NTOK * D_MODEL];
__device__ float g_k   [NTOK * D_MODEL];
__device__ float g_v   [NTOK * D_MODEL];
__device__ float g_attn[NTOK * D_MODEL];
__device__ float g_h   [NTOK * D_MODEL];
__device__ float g_hln [NTOK * D_MODEL];
__device__ float g_r   [NTOK * D_MODEL];
__device__ float g_z   [NTOK * D_MODEL];
__device__ float g_mh  [(size_t)NTOK * 4096];

// bf16 hi/lo splits: activations and weights
__device__ __nv_bfloat16 g_aH[(size_t)NTOK * 4096];
__device__ __nv_bfloat16 g_aL[(size_t)NTOK * 4096];
__device__ __nv_bfloat16 g_bH[(size_t)4096 * 1024];
__device__ __nv_bfloat16 g_bL[(size_t)4096 * 1024];

// ---------------------------------------------------------------------------
// PTX helpers (arch-agnostic: ldmatrix sm_75+, mma sm_80+, cp.async sm_80+)
// ---------------------------------------------------------------------------
__device__ __forceinline__ uint32_t smem_u32(const void* p) {
    uint32_t a;
    asm("{ .reg .u64 t; cvta.to.shared.u64 t, %1; cvt.u32.u64 %0, t; }" : "=r"(a) : "l"(p));
    return a;
}
#define CP_ASYNC16(dst, src) \
    asm volatile("cp.async.cg.shared.global [%0], [%1], 16;" :: "r"(dst), "l"(src) : "memory")
#define CP_COMMIT() asm volatile("cp.async.commit_group;" ::: "memory")
#define CP_WAIT0()  asm volatile("cp.async.wait_group 0;" ::: "memory")
#define CP_WAIT1()  asm volatile("cp.async.wait_group 1;" ::: "memory")

__device__ __forceinline__ void ldsm_x4(uint32_t* r, uint32_t addr) {
    asm volatile("ldmatrix.sync.aligned.m8n8.x4.shared.b16 {%0,%1,%2,%3}, [%4];"
                 : "=r"(r[0]), "=r"(r[1]), "=r"(r[2]), "=r"(r[3]) : "r"(addr));
}
__device__ __forceinline__ void ldsm_x2t(uint32_t* r, uint32_t addr) {
    asm volatile("ldmatrix.sync.aligned.m8n8.x2.trans.shared.b16 {%0,%1}, [%2];"
                 : "=r"(r[0]), "=r"(r[1]) : "r"(addr));
}
__device__ __forceinline__ void mma_bf16(float* c, const uint32_t* a, const uint32_t* b) {
    asm volatile("mma.sync.aligned.m16n8k16.row.col.f32.bf16.bf16.f32 "
                 "{%0,%1,%2,%3}, {%4,%5,%6,%7}, {%8,%9}, {%0,%1,%2,%3};"
                 : "+f"(c[0]), "+f"(c[1]), "+f"(c[2]), "+f"(c[3])
                 : "r"(a[0]), "r"(a[1]), "r"(a[2]), "r"(a[3]), "r"(b[0]), "r"(b[1]));
}
__device__ __forceinline__ void mma_f16(float* c, const uint32_t* a, const uint32_t* b) {
    asm volatile("mma.sync.aligned.m16n8k16.row.col.f32.f16.f16.f32 "
                 "{%0,%1,%2,%3}, {%4,%5,%6,%7}, {%8,%9}, {%0,%1,%2,%3};"
                 : "+f"(c[0]), "+f"(c[1]), "+f"(c[2]), "+f"(c[3])
                 : "r"(a[0]), "r"(a[1]), "r"(a[2]), "r"(a[3]), "r"(b[0]), "r"(b[1]));
}
__device__ __forceinline__ uint32_t pack_h2(float a, float b) {
    __half2 h = __floats2half2_rn(a, b);
    return *(uint32_t*)&h;
}

// Fast exp on the FMA pipe (no MUFU). Input x <= 0 (incl. -1e9/-2e9 masks).
// exp(x) = 2^(x*log2e); range-reduced, degree-5 poly, ~2e-6 rel accuracy.
// Clamped exponent makes deeply negative inputs return exact 0.
__device__ __forceinline__ float fast_exp(float x) {
    float y = fmaxf(x * 1.4426950408889634f, -127.0f);
    float t = y + 12582912.0f;                 // round-to-nearest-int magic
    int   n = __float_as_int(t) - 0x4B400000;
    float f = y - (t - 12582912.0f);           // f in [-0.5, 0.5]
    float p =             1.3333558146428443e-3f;
    p = fmaf(p, f, 9.618129107628477e-3f);
    p = fmaf(p, f, 5.550410866482158e-2f);
    p = fmaf(p, f, 2.402265069591007e-1f);
    p = fmaf(p, f, 6.931471805599453e-1f);
    p = fmaf(p, f, 1.0f);
    return p * __int_as_float((n + 127) << 23);
}

// ---------------------------------------------------------------------------
// HMMA GEMM (bf16 3x compensation) — unchanged from passing round 4
// ---------------------------------------------------------------------------
#define SA_H 0
#define SA_L 18432
#define SB_H 36864
#define SB_L 54272
#define STAGE 71680
#define GEMM_SMEM (2 * STAGE)

__device__ __forceinline__ void issue_chunk(uint32_t sb,
    const __nv_bfloat16* __restrict__ Ah, const __nv_bfloat16* __restrict__ Al,
    const __nv_bfloat16* __restrict__ Bh, const __nv_bfloat16* __restrict__ Bl,
    size_t row0, size_t col0, int K, int N, int k0, int tid)
{
    #pragma unroll
    for (int i = 0; i < 4; i++) {
        int idx = i * 256 + tid;
        int r   = idx >> 3;
        int c8  = (idx & 7) * 8;
        uint32_t so = sb + (uint32_t)(r * 144 + c8 * 2);
        size_t   go = (row0 + r) * (size_t)K + k0 + c8;
        CP_ASYNC16(so + SA_H, Ah + go);
        CP_ASYNC16(so + SA_L, Al + go);
    }
    #pragma unroll
    for (int i = 0; i < 4; i++) {
        int idx = i * 256 + tid;
        int r   = idx >> 4;
        int c8  = (idx & 15) * 8;
        uint32_t so = sb + (uint32_t)(r * 272 + c8 * 2);
        size_t   go = (size_t)(k0 + r) * N + col0 + c8;
        CP_ASYNC16(so + SB_H, Bh + go);
        CP_ASYNC16(so + SB_L, Bl + go);
    }
}

template <int EPI>  // 0 = bias, 1 = bias+residual, 2 = bias+exact GELU
__global__ void __launch_bounds__(256, 1) gemm_mma_kernel(
    const __nv_bfloat16* __restrict__ Ah, const __nv_bfloat16* __restrict__ Al,
    const __nv_bfloat16* __restrict__ Bh, const __nv_bfloat16* __restrict__ Bl,
    const float* __restrict__ bias, const float* __restrict__ res,
    float* __restrict__ C, int N, int K)
{
    extern __shared__ char smem[];
    const uint32_t sbase = smem_u32(smem);
    const int tid  = threadIdx.x;
    const int wid  = tid >> 5;
    const int lane = tid & 31;
    const int wm   = wid >> 2;
    const int wn   = wid & 3;
    const size_t row0 = (size_t)blockIdx.y * 128;
    const size_t col0 = (size_t)blockIdx.x * 128;

    float acc[4][4][4];
    #pragma unroll
    for (int i = 0; i < 4; i++)
        #pragma unroll
        for (int j = 0; j < 4; j++)
            #pragma unroll
            for (int c = 0; c < 4; c++) acc[i][j][c] = 0.f;

    const int nch = K >> 6;
    issue_chunk(sbase, Ah, Al, Bh, Bl, row0, col0, K, N, 0, tid);
    CP_COMMIT();

    const int aRow = (lane & 15);
    const int aColB = ((lane >> 4) << 3) * 2;
    const int l16  = lane & 15;
    const int bRow = (l16 & 7) + ((l16 >> 3) & 1) * 8;

    for (int ch = 0; ch < nch; ch++) {
        if (ch + 1 < nch) {
            issue_chunk(sbase + ((ch + 1) & 1) * STAGE, Ah, Al, Bh, Bl,
                        row0, col0, K, N, (ch + 1) << 6, tid);
            CP_COMMIT();
            CP_WAIT1();
        } else {
            CP_WAIT0();
        }
        __syncthreads();

        const uint32_t st = sbase + (ch & 1) * STAGE;
        #pragma unroll
        for (int kk = 0; kk < 64; kk += 16) {
            uint32_t ah[4][4], al[4][4], bh[4][2], bl[4][2];
            #pragma unroll
            for (int mi = 0; mi < 4; mi++) {
                uint32_t ao = st + (uint32_t)((wm * 64 + mi * 16 + aRow) * 144 + kk * 2 + aColB);
                ldsm_x4(ah[mi], ao + SA_H);
                ldsm_x4(al[mi], ao + SA_L);
            }
            #pragma unroll
            for (int ni = 0; ni < 4; ni++) {
                uint32_t bo = st + (uint32_t)((kk + bRow) * 272 + (wn * 32 + ni * 8) * 2);
                ldsm_x2t(bh[ni], bo + SB_H);
                ldsm_x2t(bl[ni], bo + SB_L);
            }
            #pragma unroll
            for (int mi = 0; mi < 4; mi++)
                #pragma unroll
                for (int ni = 0; ni < 4; ni++) {
                    mma_bf16(acc[mi][ni], ah[mi], bh[ni]);
                    mma_bf16(acc[mi][ni], ah[mi], bl[ni]);
                    mma_bf16(acc[mi][ni], al[mi], bh[ni]);
                }
        }
        __syncthreads();
    }

    #pragma unroll
    for (int mi = 0; mi < 4; mi++) {
        #pragma unroll
        for (int ni = 0; ni < 4; ni++) {
            int m  = wm * 64 + mi * 16 + (lane >> 2);
            size_t gc = col0 + wn * 32 + ni * 8 + (lane & 3) * 2;
            float b0 = bias[gc], b1 = bias[gc + 1];
            #pragma unroll
            for (int half = 0; half < 2; half++) {
                size_t gr = row0 + m + half * 8;
                float vx = acc[mi][ni][half * 2 + 0] + b0;
                float vy = acc[mi][ni][half * 2 + 1] + b1;
                if (EPI == 1) {
                    float2 rv = *(const float2*)(res + gr * (size_t)N + gc);
                    vx += rv.x; vy += rv.y;
                }
                if (EPI == 2) {
                    vx = vx * 0.5f * (1.0f + erff(vx * 0.70710678118654752f));
                    vy = vy * 0.5f * (1.0f + erff(vy * 0.70710678118654752f));
                }
                float2 o = make_float2(vx, vy);
                *(float2*)(C + gr * (size_t)N + gc) = o;
            }
        }
    }
}

// ---------------------------------------------------------------------------
// Split fp32 -> bf16 hi/lo (elementwise)
// ---------------------------------------------------------------------------
__global__ void __launch_bounds__(256) conva_kernel(
    const float* __restrict__ X, __nv_bfloat16* __restrict__ hi,
    __nv_bfloat16* __restrict__ lo)
{
    size_t i = ((size_t)blockIdx.x * 256 + threadIdx.x) * 4;
    float4 v = *(const float4*)(X + i);
    __nv_bfloat16 h0 = __float2bfloat16(v.x), h1 = __float2bfloat16(v.y);
    __nv_bfloat16 h2 = __float2bfloat16(v.z), h3 = __float2bfloat16(v.w);
    __nv_bfloat16 l0 = __float2bfloat16(v.x - __bfloat162float(h0));
    __nv_bfloat16 l1 = __float2bfloat16(v.y - __bfloat162float(h1));
    __nv_bfloat16 l2 = __float2bfloat16(v.z - __bfloat162float(h2));
    __nv_bfloat16 l3 = __float2bfloat16(v.w - __bfloat162float(h3));
    *(__nv_bfloat162*)(hi + i)     = __nv_bfloat162(h0, h1);
    *(__nv_bfloat162*)(hi + i + 2) = __nv_bfloat162(h2, h3);
    *(__nv_bfloat162*)(lo + i)     = __nv_bfloat162(l0, l1);
    *(__nv_bfloat162*)(lo + i + 2) = __nv_bfloat162(l2, l3);
}

// ---------------------------------------------------------------------------
// Block reduce / LayerNorm / embed
// ---------------------------------------------------------------------------
__device__ __forceinline__ float2 block_reduce_sum2(float a, float b) {
    #pragma unroll
    for (int o = 16; o > 0; o >>= 1) {
        a += __shfl_xor_sync(0xffffffffu, a, o);
        b += __shfl_xor_sync(0xffffffffu, b, o);
    }
    __shared__ float sa[8], sb[8];
    int w = threadIdx.x >> 5;
    if ((threadIdx.x & 31) == 0) { sa[w] = a; sb[w] = b; }
    __syncthreads();
    float ta = 0.f, tb = 0.f;
    #pragma unroll
    for (int k = 0; k < 8; k++) { ta += sa[k]; tb += sb[k]; }
    return make_float2(ta, tb);
}

__global__ void __launch_bounds__(256) embed_ln_kernel(
    const int* __restrict__ ids, const float* __restrict__ tok,
    const float* __restrict__ pos, const float* __restrict__ g,
    const float* __restrict__ be, float* __restrict__ out)
{
    int row = blockIdx.x;
    int s   = row & (SEQ - 1);
    int id  = ids[row];
    int i   = threadIdx.x;
    float4 tv = ((const float4*)(tok + (size_t)id * D_MODEL))[i];
    float4 pv = ((const float4*)(pos + (size_t)s  * D_MODEL))[i];
    float4 v  = make_float4(tv.x + pv.x, tv.y + pv.y, tv.z + pv.z, tv.w + pv.w);
    float2 ss = block_reduce_sum2(v.x + v.y + v.z + v.w,
                                  v.x*v.x + v.y*v.y + v.z*v.z + v.w*v.w);
    float mean = ss.x * (1.f / D_MODEL);
    float var  = ss.y * (1.f / D_MODEL) - mean * mean;
    float rstd = rsqrtf(var + 1e-5f);
    float4 gv = ((const float4*)g)[i];
    float4 bv = ((const float4*)be)[i];
    float4 o  = make_float4((v.x - mean) * rstd * gv.x + bv.x,
                            (v.y - mean) * rstd * gv.y + bv.y,
                            (v.z - mean) * rstd * gv.z + bv.z,
                            (v.w - mean) * rstd * gv.w + bv.w);
    ((float4*)(out + (size_t)row * D_MODEL))[i] = o;
}

__global__ void __launch_bounds__(256) ln_kernel(
    const float* __restrict__ in, const float* __restrict__ g,
    const float* __restrict__ be, float* __restrict__ out)
{
    int row = blockIdx.x;
    int i   = threadIdx.x;
    float4 v = ((const float4*)(in + (size_t)row * D_MODEL))[i];
    float2 ss = block_reduce_sum2(v.x + v.y + v.z + v.w,
                                  v.x*v.x + v.y*v.y + v.z*v.z + v.w*v.w);
    float mean = ss.x * (1.f / D_MODEL);
    float var  = ss.y * (1.f / D_MODEL) - mean * mean;
    float rstd = rsqrtf(var + 1e-5f);
    float4 gv = ((const float4*)g)[i];
    float4 bv = ((const float4*)be)[i];
    float4 o  = make_float4((v.x - mean) * rstd * gv.x + bv.x,
                            (v.y - mean) * rstd * gv.y + bv.y,
                            (v.z - mean) * rstd * gv.z + bv.z,
                            (v.w - mean) * rstd * gv.w + bv.w);
    ((float4*)(out + (size_t)row * D_MODEL))[i] = o;
}

// ---------------------------------------------------------------------------
// Tensor-core flash attention (fp16 HMMA + online softmax with poly exp).
// CTA = 128 threads (4 warps), q-tile 64 rows (16 rows/warp), k-tile 64.
// Qs [m][d] fp16 (pre-scaled 1/8); Ks transposed [d][j]; Vs natural [j][d].
// grid = (SEQ/64, NB*NHEAD)
// ---------------------------------------------------------------------------
__global__ void __launch_bounds__(128) flash_mma_kernel(
    const float* __restrict__ Qg, const float* __restrict__ Kg,
    const float* __restrict__ Vg, const int* __restrict__ ids,
    float* __restrict__ Og, int causal)
{
    __shared__ __align__(16) __half Qs[64 * 72];
    __shared__ __align__(16) __half Ks[64 * 72];   // transposed: [d][j]
    __shared__ __align__(16) __half Vs[64 * 72];   // natural:    [j][d]
    __shared__ float padS[64];

    const int tid  = threadIdx.x;
    const int wid  = tid >> 5;
    const int lane = tid & 31;
    const int qb = blockIdx.x;
    const int b  = blockIdx.y >> 4;
    const int h  = blockIdx.y & 15;
    const int i0 = qb * 64;

    const uint32_t sQ = smem_u32(Qs);
    const uint32_t sK = smem_u32(Ks);
    const uint32_t sV = smem_u32(Vs);

    const float* Qb = Qg + (size_t)b * SEQ * D_MODEL + h * DHEAD;
    const float* Kb = Kg + (size_t)b * SEQ * D_MODEL + h * DHEAD;
    const float* Vb = Vg + (size_t)b * SEQ * D_MODEL + h * DHEAD;

    // load Q tile (scaled by 1/sqrt(dh)=1/8), fp16, [m][d]
    #pragma unroll
    for (int i = 0; i < 8; i++) {
        int idx = i * 128 + tid;
        int r = idx >> 4, c4 = (idx & 15) * 4;
        float4 qv = *(const float4*)(Qb + (size_t)(i0 + r) * D_MODEL + c4);
        *(__half2*)(Qs + r * 72 + c4)     = __floats2half2_rn(qv.x * 0.125f, qv.y * 0.125f);
        *(__half2*)(Qs + r * 72 + c4 + 2) = __floats2half2_rn(qv.z * 0.125f, qv.w * 0.125f);
    }

    float oacc[8][4];
    #pragma unroll
    for (int d = 0; d < 8; d++)
        #pragma unroll
        for (int c = 0; c < 4; c++) oacc[d][c] = 0.f;
    float m0 = -1e30f, m1 = -1e30f, l0 = 0.f, l1 = 0.f;

    const int rg0 = i0 + wid * 16 + (lane >> 2);
    const int rg1 = rg0 + 8;
    const int l16 = lane & 15;

    const int nkb = causal ? (qb + 1) : (SEQ / 64);
    for (int kb = 0; kb < nkb; kb++) {
        __syncthreads();   // protect prior iteration's Vs reads
        // K tile transposed into [d][j]; V natural [j][d]
        #pragma unroll
        for (int i = 0; i < 8; i++) {
            int idx = i * 128 + tid;
            int r = idx >> 4, c4 = (idx & 15) * 4;   // r = key row j, c4 = d
            float4 kv = *(const float4*)(Kb + (size_t)(kb * 64 + r) * D_MODEL + c4);
            Ks[(c4 + 0) * 72 + r] = __float2half_rn(kv.x);
            Ks[(c4 + 1) * 72 + r] = __float2half_rn(kv.y);
            Ks[(c4 + 2) * 72 + r] = __float2half_rn(kv.z);
            Ks[(c4 + 3) * 72 + r] = __float2half_rn(kv.w);
            float4 vv = *(const float4*)(Vb + (size_t)(kb * 64 + r) * D_MODEL + c4);
            *(__half2*)(Vs + r * 72 + c4)     = __floats2half2_rn(vv.x, vv.y);
            *(__half2*)(Vs + r * 72 + c4 + 2) = __floats2half2_rn(vv.z, vv.w);
        }
        if (tid < 64)
            padS[tid] = (ids[b * SEQ + kb * 64 + tid] == 0) ? NEGV : 0.f;
        __syncthreads();

        // S = Q K^T (fp16 mma, f32 acc)
        float sacc[8][4];
        #pragma unroll
        for (int ni = 0; ni < 8; ni++)
            #pragma unroll
            for (int c = 0; c < 4; c++) sacc[ni][c] = 0.f;

        #pragma unroll
        for (int kk8 = 0; kk8 < 4; kk8++) {
            uint32_t af[4];
            uint32_t ao = sQ + (uint32_t)(((wid * 16 + l16) * 72 + kk8 * 16 + ((lane >> 4) << 3)) * 2);
            ldsm_x4(af, ao);
            #pragma unroll
            for (int ni = 0; ni < 8; ni++) {
                uint32_t bf[2];
                uint32_t bo = sK + (uint32_t)(((kk8 * 16 + l16) * 72 + ni * 8) * 2);
                ldsm_x2t(bf, bo);
                mma_f16(sacc[ni], af, bf);
            }
        }

        // masks (additive, mirroring reference semantics)
        const bool diag = (causal && kb == qb);
        #pragma unroll
        for (int ni = 0; ni < 8; ni++) {
            int c0 = ni * 8 + (lane & 3) * 2;
            float pm0 = padS[c0], pm1 = padS[c0 + 1];
            sacc[ni][0] += pm0; sacc[ni][1] += pm1;
            sacc[ni][2] += pm0; sacc[ni][3] += pm1;
            if (diag) {
                int gj0 = kb * 64 + c0, gj1 = gj0 + 1;
                if (gj0 > rg0) sacc[ni][0] += NEGV;
                if (gj1 > rg0) sacc[ni][1] += NEGV;
                if (gj0 > rg1) sacc[ni][2] += NEGV;
                if (gj1 > rg1) sacc[ni][3] += NEGV;
            }
        }

        // online softmax (rows rg0, rg1 per thread; quad = full 64-col row)
        float mx0 = -1e30f, mx1 = -1e30f;
        #pragma unroll
        for (int ni = 0; ni < 8; ni++) {
            mx0 = fmaxf(mx0, fmaxf(sacc[ni][0], sacc[ni][1]));
            mx1 = fmaxf(mx1, fmaxf(sacc[ni][2], sacc[ni][3]));
        }
        mx0 = fmaxf(mx0, __shfl_xor_sync(0xffffffffu, mx0, 1));
        mx0 = fmaxf(mx0, __shfl_xor_sync(0xffffffffu, mx0, 2));
        mx1 = fmaxf(mx1, __shfl_xor_sync(0xffffffffu, mx1, 1));
        mx1 = fmaxf(mx1, __shfl_xor_sync(0xffffffffu, mx1, 2));

        float m0n = fmaxf(m0, mx0), m1n = fmaxf(m1, mx1);
        float al0 = fast_exp(m0 - m0n), al1 = fast_exp(m1 - m1n);
        m0 = m0n; m1 = m1n;

        float rs0 = 0.f, rs1 = 0.f;
        #pragma unroll
        for (int ni = 0; ni < 8; ni++) {
            sacc[ni][0] = fast_exp(sacc[ni][0] - m0n); rs0 += sacc[ni][0];
            sacc[ni][1] = fast_exp(sacc[ni][1] - m0n); rs0 += sacc[ni][1];
            sacc[ni][2] = fast_exp(sacc[ni][2] - m1n); rs1 += sacc[ni][2];
            sacc[ni][3] = fast_exp(sacc[ni][3] - m1n); rs1 += sacc[ni][3];
        }
        rs0 += __shfl_xor_sync(0xffffffffu, rs0, 1);
        rs0 += __shfl_xor_sync(0xffffffffu, rs0, 2);
        rs1 += __shfl_xor_sync(0xffffffffu, rs1, 1);
        rs1 += __shfl_xor_sync(0xffffffffu, rs1, 2);
        l0 = l0 * al0 + rs0;
        l1 = l1 * al1 + rs1;

        #pragma unroll
        for (int d = 0; d < 8; d++) {
            oacc[d][0] *= al0; oacc[d][1] *= al0;
            oacc[d][2] *= al1; oacc[d][3] *= al1;
        }

        // O += P V  (P fragments repacked in registers: C-layout == A-layout)
        #pragma unroll
        for (int ka = 0; ka < 4; ka++) {
            uint32_t pf[4];
            pf[0] = pack_h2(sacc[2 * ka][0],     sacc[2 * ka][1]);
            pf[1] = pack_h2(sacc[2 * ka][2],     sacc[2 * ka][3]);
            pf[2] = pack_h2(sacc[2 * ka + 1][0], sacc[2 * ka + 1][1]);
            pf[3] = pack_h2(sacc[2 * ka + 1][2], sacc[2 * ka + 1][3]);
            #pragma unroll
            for (int d = 0; d < 8; d++) {
                uint32_t bf[2];
                uint32_t bo = sV + (uint32_t)(((ka * 16 + l16) * 72 + d * 8) * 2);
                ldsm_x2t(bf, bo);
                mma_f16(oacc[d], pf, bf);
            }
        }
    }

    // write O (fp32), normalized
    float inv0 = 1.f / l0, inv1 = 1.f / l1;
    #pragma unroll
    for (int d = 0; d < 8; d++) {
        size_t gc = (size_t)h * DHEAD + d * 8 + (lane & 3) * 2;
        *(float2*)(Og + (size_t)(b * SEQ + rg0) * D_MODEL + gc) =
            make_float2(oacc[d][0] * inv0, oacc[d][1] * inv0);
        *(float2*)(Og + (size_t)(b * SEQ + rg1) * D_MODEL + gc) =
            make_float2(oacc[d][2] * inv1, oacc[d][3] * inv1);
    }
}

// ---------------------------------------------------------------------------
// Launch
// ---------------------------------------------------------------------------
extern "C" void kernel_launch(void* const* d_in, const int* in_sizes, int n_in,
                              void* d_out, int out_size)
{
    (void)in_sizes; (void)n_in; (void)out_size;

    const float* input_embedding = (const float*)d_in[0];
    const int*   input_ids       = (const int*)  d_in[1];
    const int*   target_ids      = (const int*)  d_in[2];
    const float* tok_emb         = (const float*)d_in[3];
    const float* pos_emb         = (const float*)d_in[4];
    const float* ln1_g = (const float*)d_in[5];
    const float* ln1_b = (const float*)d_in[6];
    const float* q1_w  = (const float*)d_in[7];
    const float* q1_b  = (const float*)d_in[8];
    const float* k1_w  = (const float*)d_in[9];
    const float* k1_b  = (const float*)d_in[10];
    const float* v1_w  = (const float*)d_in[11];
    const float* v1_b  = (const float*)d_in[12];
    const float* out1_w = (const float*)d_in[13];
    const float* out1_b = (const float*)d_in[14];
    const float* ln2_g = (const float*)d_in[15];
    const float* ln2_b = (const float*)d_in[16];
    const float* q2_w  = (const float*)d_in[17];
    const float* q2_b  = (const float*)d_in[18];
    const float* k2_w  = (const float*)d_in[19];
    const float* k2_b  = (const float*)d_in[20];
    const float* v2_w  = (const float*)d_in[21];
    const float* v2_b  = (const float*)d_in[22];
    const float* out2_w = (const float*)d_in[23];
    const float* out2_b = (const float*)d_in[24];
    const float* ln3_g = (const float*)d_in[25];
    const float* ln3_b = (const float*)d_in[26];
    const float* mlp_w1 = (const float*)d_in[27];
    const float* mlp_b1 = (const float*)d_in[28];
    const float* mlp_w2 = (const float*)d_in[29];
    const float* mlp_b2 = (const float*)d_in[30];

    float *x, *q, *k, *v, *attn, *h, *hln, *r, *z, *mh;
    __nv_bfloat16 *aH, *aL, *bH, *bL;
    cudaGetSymbolAddress((void**)&x,    g_x);
    cudaGetSymbolAddress((void**)&q,    g_q);
    cudaGetSymbolAddress((void**)&k,    g_k);
    cudaGetSymbolAddress((void**)&v,    g_v);
    cudaGetSymbolAddress((void**)&attn, g_attn);
    cudaGetSymbolAddress((void**)&h,    g_h);
    cudaGetSymbolAddress((void**)&hln,  g_hln);
    cudaGetSymbolAddress((void**)&r,    g_r);
    cudaGetSymbolAddress((void**)&z,    g_z);
    cudaGetSymbolAddress((void**)&mh,   g_mh);
    cudaGetSymbolAddress((void**)&aH,   g_aH);
    cudaGetSymbolAddress((void**)&aL,   g_aL);
    cudaGetSymbolAddress((void**)&bH,   g_bH);
    cudaGetSymbolAddress((void**)&bL,   g_bL);

    float* out = (float*)d_out;

    cudaFuncSetAttribute(gemm_mma_kernel<0>, cudaFuncAttributeMaxDynamicSharedMemorySize, GEMM_SMEM);
    cudaFuncSetAttribute(gemm_mma_kernel<1>, cudaFuncAttributeMaxDynamicSharedMemorySize, GEMM_SMEM);
    cudaFuncSetAttribute(gemm_mma_kernel<2>, cudaFuncAttributeMaxDynamicSharedMemorySize, GEMM_SMEM);

    const dim3 gN1024(1024 / 128, NTOK / 128);   // (8, 32)
    const dim3 gN4096(4096 / 128, NTOK / 128);   // (32, 32)
    const dim3 gAttn(SEQ / 64, NB * NHEAD);
    const int  cAct1024 = (NTOK * 1024) / 1024;
    const int  cAct4096 = (NTOK * 4096) / 1024;
    const int  cW1M = (1024 * 1024) / 1024;
    const int  cW4M = (4096 * 1024) / 1024;

    // x = LN1(embed)
    embed_ln_kernel<<<NTOK, 256>>>(target_ids, tok_emb, pos_emb, ln1_g, ln1_b, x);

    // ---- self attention ----
    conva_kernel<<<cAct1024, 256>>>(x, aH, aL);
    conva_kernel<<<cW1M, 256>>>(q1_w, bH, bL);
    gemm_mma_kernel<0><<<gN1024, 256, GEMM_SMEM>>>(aH, aL, bH, bL, q1_b, nullptr, q, 1024, 1024);
    conva_kernel<<<cW1M, 256>>>(k1_w, bH, bL);
    gemm_mma_kernel<0><<<gN1024, 256, GEMM_SMEM>>>(aH, aL, bH, bL, k1_b, nullptr, k, 1024, 1024);
    conva_kernel<<<cW1M, 256>>>(v1_w, bH, bL);
    gemm_mma_kernel<0><<<gN1024, 256, GEMM_SMEM>>>(aH, aL, bH, bL, v1_b, nullptr, v, 1024, 1024);
    flash_mma_kernel<<<gAttn, 128>>>(q, k, v, target_ids, attn, 1);

    conva_kernel<<<cAct1024, 256>>>(attn, aH, aL);
    conva_kernel<<<cW1M, 256>>>(out1_w, bH, bL);
    gemm_mma_kernel<1><<<gN1024, 256, GEMM_SMEM>>>(aH, aL, bH, bL, out1_b, x, h, 1024, 1024);
    ln_kernel<<<NTOK, 256>>>(h, ln2_g, ln2_b, hln);

    // ---- cross attention ----
    conva_kernel<<<cAct1024, 256>>>(hln, aH, aL);
    conva_kernel<<<cW1M, 256>>>(q2_w, bH, bL);
    gemm_mma_kernel<0><<<gN1024, 256, GEMM_SMEM>>>(aH, aL, bH, bL, q2_b, nullptr, q, 1024, 1024);
    conva_kernel<<<cAct1024, 256>>>(input_embedding, aH, aL);
    conva_kernel<<<cW1M, 256>>>(k2_w, bH, bL);
    gemm_mma_kernel<0><<<gN1024, 256, GEMM_SMEM>>>(aH, aL, bH, bL, k2_b, nullptr, k, 1024, 1024);
    conva_kernel<<<cW1M, 256>>>(v2_w, bH, bL);
    gemm_mma_kernel<0><<<gN1024, 256, GEMM_SMEM>>>(aH, aL, bH, bL, v2_b, nullptr, v, 1024, 1024);
    flash_mma_kernel<<<gAttn, 128>>>(q, k, v, input_ids, attn, 0);

    conva_kernel<<<cAct1024, 256>>>(attn, aH, aL);
    conva_kernel<<<cW1M, 256>>>(out2_w, bH, bL);
    gemm_mma_kernel<1><<<gN1024, 256, GEMM_SMEM>>>(aH, aL, bH, bL, out2_b, hln, r, 1024, 1024);

    // ---- MLP ----
    ln_kernel<<<NTOK, 256>>>(r, ln3_g, ln3_b, z);
    conva_kernel<<<cAct1024, 256>>>(z, aH, aL);
    conva_kernel<<<cW4M, 256>>>(mlp_w1, bH, bL);
    gemm_mma_kernel<2><<<gN4096, 256, GEMM_SMEM>>>(aH, aL, bH, bL, mlp_b1, nullptr, mh, 4096, 1024);
    conva_kernel<<<cAct4096, 256>>>(mh, aH, aL);
    conva_kernel<<<cW4M, 256>>>(mlp_w2, bH, bL);
    gemm_mma_kernel<1><<<gN1024, 256, GEMM_SMEM>>>(aH, aL, bH, bL, mlp_b2, r, out, 1024, 4096);
}